// round 15
// baseline (speedup 1.0000x reference)
#include <cuda_runtime.h>
#include <cuda_bf16.h>
#include <cstdint>

#define D_     256
#define S_     8
#define DS_    264
#define DEPTH_ 4
#define VOCAB_ 32000
#define MROWS  4096
#define L_     2048
#define B_     2
#define KP2    288   // padded K for GEMM2
#define NP1    320   // padded N for GEMM1 B panel (5 x 64)

// ---------------- scratch (device globals) ----------------------------------
__device__ float g_h[MROWS * D_];             // h fp32 (ln input)
__device__ float g_comb[MROWS * DS_];         // combined fp32 (gate input)
__device__ float g_ga[S_ * MROWS];            // gates col-major [s][row]
__device__ float g_gb[S_ * MROWS];            // (1-g)*state_in col-major
__device__ __nv_bfloat16 g_xhi[MROWS * D_];   // h split hi (GEMM1 A)
__device__ __nv_bfloat16 g_xlo[MROWS * D_];
__device__ __nv_bfloat16 g_c2hi[MROWS * KP2]; // comb split (GEMM2 A), K padded
__device__ __nv_bfloat16 g_c2lo[MROWS * KP2];
__device__ __nv_bfloat16 g_ahi[MROWS * D_];   // ln output split (logits/recon A)
__device__ __nv_bfloat16 g_alo[MROWS * D_];
// weight splits, B layout [Npad][KPAD]
__device__ __nv_bfloat16 g_w1hi[DEPTH_ * NP1 * D_];   // WiT (264->320 rows)
__device__ __nv_bfloat16 g_w1lo[DEPTH_ * NP1 * D_];
__device__ __nv_bfloat16 g_w2hi[DEPTH_ * D_ * KP2];   // WoT (K 264->288)
__device__ __nv_bfloat16 g_w2lo[DEPTH_ * D_ * KP2];
__device__ __nv_bfloat16 g_wrhi[D_ * D_];             // WrT
__device__ __nv_bfloat16 g_wrlo[D_ * D_];
__device__ __nv_bfloat16 g_bhi[VOCAB_ * D_];          // WcT
__device__ __nv_bfloat16 g_blo[VOCAB_ * D_];

// ---------------- PTX helpers (baseline sm_80-era only) ----------------------
__device__ __forceinline__ uint32_t smem_u32(const void* p) {
    uint32_t a;
    asm("{ .reg .u64 t; cvta.to.shared.u64 t, %1; cvt.u32.u64 %0, t; }" : "=r"(a) : "l"(p));
    return a;
}
#define CP_ASYNC16(dst, src) \
    asm volatile("cp.async.cg.shared.global [%0], [%1], 16;" :: "r"(dst), "l"(src))
#define CP_COMMIT() asm volatile("cp.async.commit_group;" ::: "memory")
__device__ __forceinline__ void cp_wait_n(int n) {
    if (n <= 0)      asm volatile("cp.async.wait_group 0;" ::: "memory");
    else if (n == 1) asm volatile("cp.async.wait_group 1;" ::: "memory");
    else if (n == 2) asm volatile("cp.async.wait_group 2;" ::: "memory");
    else if (n == 3) asm volatile("cp.async.wait_group 3;" ::: "memory");
    else             asm volatile("cp.async.wait_group 4;" ::: "memory");
}
#define LDSM4(r0, r1, r2, r3, addr) \
    asm volatile("ldmatrix.sync.aligned.m8n8.x4.shared.b16 {%0,%1,%2,%3}, [%4];" \
                 : "=r"(r0), "=r"(r1), "=r"(r2), "=r"(r3) : "r"(addr))
#define MMA16816(d, a, b) \
    asm volatile("mma.sync.aligned.m16n8k16.row.col.f32.bf16.bf16.f32 " \
                 "{%0,%1,%2,%3}, {%4,%5,%6,%7}, {%8,%9}, {%0,%1,%2,%3};" \
                 : "+f"((d)[0]), "+f"((d)[1]), "+f"((d)[2]), "+f"((d)[3]) \
                 : "r"((a)[0]), "r"((a)[1]), "r"((a)[2]), "r"((a)[3]), \
                   "r"((b)[0]), "r"((b)[1]))
#define STG2CS(ptr, vx, vy) \
    asm volatile("st.global.cs.v2.f32 [%0], {%1,%2};" :: "l"(ptr), "f"(vx), "f"(vy) : "memory")

__device__ __forceinline__ void split_bf16(float v, __nv_bfloat16& hi, __nv_bfloat16& lo) {
    hi = __float2bfloat16(v);
    lo = __float2bfloat16(v - __bfloat162float(hi));
}

// ---------------- prep_all: all 9 weight transpose+splits in ONE launch ------
__global__ void __launch_bounds__(256)
prep_all(const float* __restrict__ Wi, const float* __restrict__ Wo,
         const float* __restrict__ Wr)
{
    int id = blockIdx.y;
    const float* src;
    __nv_bfloat16 *dhi, *dlo;
    int Ksrc, Nsrc, srcld, Npad, KP;
    if (id < 4) {
        src = Wi + (size_t)id * D_ * DS_;
        dhi = g_w1hi + (size_t)id * NP1 * D_; dlo = g_w1lo + (size_t)id * NP1 * D_;
        Ksrc = D_; Nsrc = DS_; srcld = DS_; Npad = NP1; KP = D_;
    } else if (id < 8) {
        int i = id - 4;
        src = Wo + (size_t)i * DS_ * D_;
        dhi = g_w2hi + (size_t)i * D_ * KP2; dlo = g_w2lo + (size_t)i * D_ * KP2;
        Ksrc = DS_; Nsrc = D_; srcld = D_; Npad = D_; KP = KP2;
    } else {
        src = Wr;
        dhi = g_wrhi; dlo = g_wrlo;
        Ksrc = D_; Nsrc = D_; srcld = D_; Npad = D_; KP = D_;
    }
    int nx = Npad / 32, ny = KP / 32;
    if ((int)blockIdx.x >= nx * ny) return;
    int n0 = ((int)blockIdx.x % nx) * 32;
    int k0 = ((int)blockIdx.x / nx) * 32;

    __shared__ float tile[32][33];
    int tx = threadIdx.x & 31, ty = threadIdx.x >> 5;
#pragma unroll
    for (int i = 0; i < 4; i++) {
        int k = k0 + ty + i * 8, n = n0 + tx;
        tile[ty + i * 8][tx] = (k < Ksrc && n < Nsrc) ? src[(size_t)k * srcld + n] : 0.f;
    }
    __syncthreads();
#pragma unroll
    for (int i = 0; i < 4; i++) {
        int n = n0 + ty + i * 8, k = k0 + tx;
        float x = tile[tx][ty + i * 8];
        __nv_bfloat16 hi, lo;
        split_bf16(x, hi, lo);
        dhi[(size_t)n * KP + k] = hi;
        dlo[(size_t)n * KP + k] = lo;
    }
}

// ---------------- Wc transpose + split (single launch) -----------------------
__global__ void __launch_bounds__(256)
split_wc(const float* __restrict__ Wc)
{
    __shared__ float tile[32][33];
    int tx = threadIdx.x & 31, ty = threadIdx.x >> 5;
    int v0 = blockIdx.x * 32, d0 = blockIdx.y * 32;
#pragma unroll
    for (int i = 0; i < 4; i++) {
        int d = d0 + ty + i * 8;
        tile[ty + i * 8][tx] = Wc[(size_t)d * VOCAB_ + v0 + tx];
    }
    __syncthreads();
#pragma unroll
    for (int i = 0; i < 4; i++) {
        int v = v0 + ty + i * 8;
        float x = tile[tx][ty + i * 8];
        __nv_bfloat16 hi, lo;
        split_bf16(x, hi, lo);
        g_bhi[(size_t)v * D_ + d0 + tx] = hi;
        g_blo[(size_t)v * D_ + d0 + tx] = lo;
    }
}

// ---------------- embed: gather + fused hi/lo split --------------------------
__global__ void embed_kernel(const int* __restrict__ x, const float* __restrict__ tab)
{
    int row = blockIdx.x;
    int t   = threadIdx.x;  // 64 threads x float4
    int tok = x[row];
    float4 v = reinterpret_cast<const float4*>(tab + (size_t)tok * D_)[t];
    reinterpret_cast<float4*>(g_h + (size_t)row * D_)[t] = v;
    __nv_bfloat16 h0, l0, h1, l1, h2, l2, h3, l3;
    split_bf16(v.x, h0, l0); split_bf16(v.y, h1, l1);
    split_bf16(v.z, h2, l2); split_bf16(v.w, h3, l3);
    __nv_bfloat162* hp = reinterpret_cast<__nv_bfloat162*>(g_xhi + (size_t)row * D_ + t * 4);
    __nv_bfloat162* lp = reinterpret_cast<__nv_bfloat162*>(g_xlo + (size_t)row * D_ + t * 4);
    hp[0] = __nv_bfloat162(h0, h1); hp[1] = __nv_bfloat162(h2, h3);
    lp[0] = __nv_bfloat162(l0, l1); lp[1] = __nv_bfloat162(l2, l3);
}

// ---------------- gate: sigmoid + compact scan inputs ------------------------
__global__ void gate_kernel(const float* __restrict__ Wg, const float* __restrict__ bg)
{
    int warp = (blockIdx.x * blockDim.x + threadIdx.x) >> 5;
    int lane = threadIdx.x & 31;
    if (warp >= MROWS) return;
    const float* row = g_comb + (size_t)warp * DS_;
    float acc[S_];
#pragma unroll
    for (int s = 0; s < S_; s++) acc[s] = 0.f;
    for (int k = lane; k < DS_; k += 32) {
        float c = row[k];
        const float* w = Wg + (size_t)k * S_;
#pragma unroll
        for (int s = 0; s < S_; s++) acc[s] += c * w[s];
    }
#pragma unroll
    for (int s = 0; s < S_; s++)
#pragma unroll
        for (int o = 16; o > 0; o >>= 1)
            acc[s] += __shfl_down_sync(0xffffffffu, acc[s], o);
    if (lane == 0) {
#pragma unroll
        for (int s = 0; s < S_; s++) {
            float g = 1.f / (1.f + __expf(-(acc[s] + bg[s])));
            float sin_v = row[D_ + s];
            g_ga[(size_t)s * MROWS + warp] = g;
            g_gb[(size_t)s * MROWS + warp] = (1.f - g) * sin_v;
        }
    }
}

// ---------------- scan: states -> c2 hi/lo (GEMM2 A) + final states ----------
__global__ void __launch_bounds__(1024)
scan_kernel(float* __restrict__ out_states)
{
    __shared__ float warp_tot[16];
    int w = threadIdx.x >> 5;
    int lane = threadIdx.x & 31;
    int pair = w >> 1;
    int half = w & 1;
    int b = pair >> 3, s = pair & 7;
    const float* ga = g_ga + (size_t)s * MROWS + (size_t)b * L_ + half * 1024;
    const float* gb = g_gb + (size_t)s * MROWS + (size_t)b * L_ + half * 1024;
    int l0 = lane * 32;

    float A = 1.f, Bv = 0.f;
#pragma unroll
    for (int i4 = 0; i4 < 8; i4++) {
        float4 gv = *reinterpret_cast<const float4*>(ga + l0 + i4 * 4);
        float4 bv = *reinterpret_cast<const float4*>(gb + l0 + i4 * 4);
        Bv = gv.x * Bv + bv.x; A *= gv.x;
        Bv = gv.y * Bv + bv.y; A *= gv.y;
        Bv = gv.z * Bv + bv.z; A *= gv.z;
        Bv = gv.w * Bv + bv.w; A *= gv.w;
    }
#pragma unroll
    for (int o = 1; o < 32; o <<= 1) {
        float Ap = __shfl_up_sync(0xffffffffu, A, o);
        float Bp = __shfl_up_sync(0xffffffffu, Bv, o);
        if (lane >= o) { Bv = A * Bp + Bv; A = A * Ap; }
    }
    if (half == 0 && lane == 31) warp_tot[pair] = Bv;
    __syncthreads();
    float y_w = (half == 0) ? 0.f : warp_tot[pair];
    float Aex = __shfl_up_sync(0xffffffffu, A, 1);
    float Bex = __shfl_up_sync(0xffffffffu, Bv, 1);
    if (lane == 0) { Aex = 1.f; Bex = 0.f; }
    float y = Aex * y_w + Bex;

    size_t rbase = (size_t)b * L_ + half * 1024 + l0;
#pragma unroll
    for (int i4 = 0; i4 < 8; i4++) {
        float4 gv = *reinterpret_cast<const float4*>(ga + l0 + i4 * 4);
        float4 bv = *reinterpret_cast<const float4*>(gb + l0 + i4 * 4);
        float ys[4];
        y = gv.x * y + bv.x; ys[0] = y;
        y = gv.y * y + bv.y; ys[1] = y;
        y = gv.z * y + bv.z; ys[2] = y;
        y = gv.w * y + bv.w; ys[3] = y;
#pragma unroll
        for (int j = 0; j < 4; j++) {
            __nv_bfloat16 hi, lo;
            split_bf16(ys[j], hi, lo);
            size_t idx = (rbase + i4 * 4 + j) * KP2 + D_ + s;
            g_c2hi[idx] = hi;
            g_c2lo[idx] = lo;
        }
    }
    if (half == 1 && lane == 31) out_states[b * S_ + s] = y;
}

// ---------------- layernorm: h fp32 -> ahi/alo -------------------------------
__global__ void ln_kernel(const float* __restrict__ gamma, const float* __restrict__ beta)
{
    int warp = (blockIdx.x * blockDim.x + threadIdx.x) >> 5;
    int lane = threadIdx.x & 31;
    if (warp >= MROWS) return;
    const float* x = g_h + (size_t)warp * D_;
    float v[8];
    *reinterpret_cast<float4*>(v)     = *reinterpret_cast<const float4*>(x + lane * 8);
    *reinterpret_cast<float4*>(v + 4) = *reinterpret_cast<const float4*>(x + lane * 8 + 4);
    float sum = 0.f;
#pragma unroll
    for (int i = 0; i < 8; i++) sum += v[i];
#pragma unroll
    for (int o = 16; o > 0; o >>= 1) sum += __shfl_xor_sync(0xffffffffu, sum, o);
    float mu = sum * (1.f / 256.f);
    float sq = 0.f;
#pragma unroll
    for (int i = 0; i < 8; i++) { float d = v[i] - mu; sq += d * d; }
#pragma unroll
    for (int o = 16; o > 0; o >>= 1) sq += __shfl_xor_sync(0xffffffffu, sq, o);
    float rstd = rsqrtf(sq * (1.f / 256.f) + 1e-5f);
    __nv_bfloat16* hip = g_ahi + (size_t)warp * D_;
    __nv_bfloat16* lop = g_alo + (size_t)warp * D_;
#pragma unroll
    for (int i = 0; i < 8; i++) {
        int c = lane * 8 + i;
        float y = (v[i] - mu) * rstd * gamma[c] + beta[c];
        __nv_bfloat16 hi, lo;
        split_bf16(y, hi, lo);
        hip[c] = hi;
        lop[c] = lo;
    }
}

// ---------------- tc_gemm: 128x128 tile, 4-stage pipeline (logits) -----------
#define STAGE_BYTES 16384
#define GSTAGES 4
template<int KPAD, int MODE>
__global__ void __launch_bounds__(256)
tc_gemm(const __nv_bfloat16* __restrict__ Ahi, const __nv_bfloat16* __restrict__ Alo,
        const __nv_bfloat16* __restrict__ Bhi, const __nv_bfloat16* __restrict__ Blo,
        const float* __restrict__ bias,
        float* __restrict__ C, int ldC)
{
    constexpr int NCH = KPAD / 32;
    constexpr int NCHUNKS = 3 * NCH;
    extern __shared__ char smem[];
    uint32_t sb = smem_u32(smem);
    int tid = threadIdx.x;
    int lane = tid & 31;
    int warp = tid >> 5;
    int wm = warp >> 2;
    int wn = warp & 3;
    int m0 = blockIdx.y * 128;
    int n0 = blockIdx.x * 128;

    int st_r0 = tid >> 2;
    int st_r1 = st_r0 + 64;
    int st_c  = tid & 3;
    uint32_t st_off0 = (uint32_t)(st_r0 * 64 + ((st_c ^ ((st_r0 >> 1) & 3)) << 4));
    uint32_t st_off1 = (uint32_t)(st_r1 * 64 + ((st_c ^ ((st_r1 >> 1) & 3)) << 4));

    const __nv_bfloat16* APl[3] = { Ahi, Alo, Ahi };
    const __nv_bfloat16* BPl[3] = { Bhi, Bhi, Blo };

    int arow[4], brow[2];
    uint32_t aswz[4], bswz[2];
#pragma unroll
    for (int fm = 0; fm < 4; fm++) {
        int r = wm * 64 + fm * 16 + (lane & 15);
        arow[fm] = r * 64;
        aswz[fm] = (r >> 1) & 3;
    }
#pragma unroll
    for (int g = 0; g < 2; g++) {
        int r = wn * 32 + g * 16 + (lane & 15);
        brow[g] = r * 64;
        bswz[g] = (r >> 1) & 3;
    }
    uint32_t chi = (uint32_t)(lane >> 4);

    float acc[4][4][4];
#pragma unroll
    for (int i = 0; i < 4; i++)
#pragma unroll
        for (int j = 0; j < 4; j++)
#pragma unroll
            for (int r = 0; r < 4; r++) acc[i][j][r] = 0.f;

#define ISSUE(ci, stg)                                                                \
    do {                                                                              \
        int _p = (ci) / NCH;                                                          \
        int _kc = ((ci) % NCH) * 32;                                                  \
        const __nv_bfloat16* _A = APl[_p];                                            \
        const __nv_bfloat16* _B = BPl[_p];                                            \
        uint32_t _sa = sb + (stg) * STAGE_BYTES;                                      \
        uint32_t _sbm = _sa + 8192;                                                   \
        CP_ASYNC16(_sa + st_off0, _A + (size_t)(m0 + st_r0) * KPAD + _kc + st_c * 8); \
        CP_ASYNC16(_sa + st_off1, _A + (size_t)(m0 + st_r1) * KPAD + _kc + st_c * 8); \
        CP_ASYNC16(_sbm + st_off0, _B + (size_t)(n0 + st_r0) * KPAD + _kc + st_c * 8); \
        CP_ASYNC16(_sbm + st_off1, _B + (size_t)(n0 + st_r1) * KPAD + _kc + st_c * 8); \
    } while (0)

#pragma unroll
    for (int p = 0; p < GSTAGES - 1; p++) { ISSUE(p, p); CP_COMMIT(); }

    for (int ci = 0; ci < NCHUNKS; ci++) {
        int rem = NCHUNKS - 1 - ci;
        cp_wait_n(rem < GSTAGES - 2 ? rem : GSTAGES - 2);
        __syncthreads();
        if (ci + GSTAGES - 1 < NCHUNKS) ISSUE(ci + GSTAGES - 1, (ci + GSTAGES - 1) & (GSTAGES - 1));
        CP_COMMIT();

        uint32_t sa = sb + (ci & (GSTAGES - 1)) * STAGE_BYTES;
        uint32_t sbm = sa + 8192;
#pragma unroll
        for (int ks = 0; ks < 2; ks++) {
            uint32_t c = 2 * ks + chi;
            uint32_t af[4][4], bf[4][2];
#pragma unroll
            for (int fm = 0; fm < 4; fm++) {
                uint32_t addr = sa + arow[fm] + ((c ^ aswz[fm]) << 4);
                LDSM4(af[fm][0], af[fm][1], af[fm][2], af[fm][3], addr);
            }
#pragma unroll
            for (int g = 0; g < 2; g++) {
                uint32_t addr = sbm + brow[g] + ((c ^ bswz[g]) << 4);
                uint32_t t0, t1, t2, t3;
                LDSM4(t0, t1, t2, t3, addr);
                bf[2 * g + 0][0] = t0; bf[2 * g + 1][0] = t1;
                bf[2 * g + 0][1] = t2; bf[2 * g + 1][1] = t3;
            }
#pragma unroll
            for (int fm = 0; fm < 4; fm++)
#pragma unroll
                for (int fn = 0; fn < 4; fn++)
                    MMA16816(acc[fm][fn], af[fm], bf[fn]);
        }
    }
#undef ISSUE

#pragma unroll
    for (int fm = 0; fm < 4; fm++) {
        int row0 = m0 + wm * 64 + fm * 16 + (lane >> 2);
#pragma unroll
        for (int fn = 0; fn < 4; fn++) {
            int col = n0 + wn * 32 + fn * 8 + (lane & 3) * 2;
            float2 b2 = *reinterpret_cast<const float2*>(bias + col);
            float v0x = acc[fm][fn][0] + b2.x, v0y = acc[fm][fn][1] + b2.y;
            float v1x = acc[fm][fn][2] + b2.x, v1y = acc[fm][fn][3] + b2.y;
            STG2CS(C + (size_t)row0 * ldC + col, v0x, v0y);
            STG2CS(C + (size_t)(row0 + 8) * ldC + col, v1x, v1y);
        }
    }
}

// ---------------- tc_sm: 64x64 tile, 6-stage pipeline (small GEMMs) ----------
#define SSTAGES 6
template<int KPAD, int MODE>
__global__ void __launch_bounds__(128)
tc_sm(const __nv_bfloat16* __restrict__ Ahi, const __nv_bfloat16* __restrict__ Alo,
      const __nv_bfloat16* __restrict__ Bhi, const __nv_bfloat16* __restrict__ Blo,
      const float* __restrict__ bias,
      float* __restrict__ C, int ldC,
      __nv_bfloat16* __restrict__ Ohi, __nv_bfloat16* __restrict__ Olo,
      int ldO, int Nvalid)
{
    constexpr int NCH = KPAD / 32;
    constexpr int NCHUNKS = 3 * NCH;
    __shared__ char smem[SSTAGES * 8192];
    uint32_t sb = smem_u32(smem);
    int tid = threadIdx.x;
    int lane = tid & 31;
    int warp = tid >> 5;
    int wm = warp >> 1;          // 0..1
    int wn = warp & 1;           // 0..1
    int m0 = blockIdx.y * 64;
    int n0 = blockIdx.x * 64;

    int st_r = tid >> 1;
    int st_c0 = (tid & 1) * 2;
    uint32_t st_off0 = (uint32_t)(st_r * 64 + ((st_c0 ^ ((st_r >> 1) & 3)) << 4));
    uint32_t st_off1 = (uint32_t)(st_r * 64 + (((st_c0 + 1) ^ ((st_r >> 1) & 3)) << 4));

    const __nv_bfloat16* APl[3] = { Ahi, Alo, Ahi };
    const __nv_bfloat16* BPl[3] = { Bhi, Bhi, Blo };

    int arow[2], brow[2];
    uint32_t aswz[2], bswz[2];
#pragma unroll
    for (int fm = 0; fm < 2; fm++) {
        int r = wm * 32 + fm * 16 + (lane & 15);
        arow[fm] = r * 64;
        aswz[fm] = (r >> 1) & 3;
    }
#pragma unroll
    for (int g = 0; g < 2; g++) {
        int r = wn * 32 + g * 16 + (lane & 15);
        brow[g] = r * 64;
        bswz[g] = (r >> 1) & 3;
    }
    uint32_t chi = (uint32_t)(lane >> 4);

    float acc[2][4][4];
#pragma unroll
    for (int i = 0; i < 2; i++)
#pragma unroll
        for (int j = 0; j < 4; j++)
#pragma unroll
            for (int r = 0; r < 4; r++) acc[i][j][r] = 0.f;

#define ISSUE_S(ci, stg)                                                                  \
    do {                                                                                  \
        int _p = (ci) / NCH;                                                              \
        int _kc = ((ci) % NCH) * 32;                                                      \
        const __nv_bfloat16* _A = APl[_p];                                                \
        const __nv_bfloat16* _B = BPl[_p];                                                \
        uint32_t _sa = sb + (stg) * 8192;                                                 \
        uint32_t _sbm = _sa + 4096;                                                       \
        CP_ASYNC16(_sa + st_off0, _A + (size_t)(m0 + st_r) * KPAD + _kc + st_c0 * 8);     \
        CP_ASYNC16(_sa + st_off1, _A + (size_t)(m0 + st_r) * KPAD + _kc + (st_c0 + 1) * 8); \
        CP_ASYNC16(_sbm + st_off0, _B + (size_t)(n0 + st_r) * KPAD + _kc + st_c0 * 8);    \
        CP_ASYNC16(_sbm + st_off1, _B + (size_t)(n0 + st_r) * KPAD + _kc + (st_c0 + 1) * 8); \
    } while (0)

#pragma unroll
    for (int p = 0; p < SSTAGES - 1; p++) {
        if (p < NCHUNKS) ISSUE_S(p, p);
        CP_COMMIT();
    }

    for (int ci = 0; ci < NCHUNKS; ci++) {
        int rem = NCHUNKS - 1 - ci;
        cp_wait_n(rem < SSTAGES - 2 ? rem : SSTAGES - 2);
        __syncthreads();
        int nx = ci + SSTAGES - 1;
        if (nx < NCHUNKS) ISSUE_S(nx, nx % SSTAGES);
        CP_COMMIT();

        uint32_t sa = sb + (ci % SSTAGES) * 8192;
        uint32_t sbm = sa + 4096;
#pragma unroll
        for (int ks = 0; ks < 2; ks++) {
            uint32_t c = 2 * ks + chi;
            uint32_t af[2][4], bf[4][2];
#pragma unroll
            for (int fm = 0; fm < 2; fm++) {
                uint32_t addr = sa + arow[fm] + ((c ^ aswz[fm]) << 4);
                LDSM4(af[fm][0], af[fm][1], af[fm][2], af[fm][3], addr);
            }
#pragma unroll
            for (int g = 0; g < 2; g++) {
                uint32_t addr = sbm + brow[g] + ((c ^ bswz[g]) << 4);
                uint32_t t0, t1, t2, t3;
                LDSM4(t0, t1, t2, t3, addr);
                bf[2 * g + 0][0] = t0; bf[2 * g + 1][0] = t1;
                bf[2 * g + 0][1] = t2; bf[2 * g + 1][1] = t3;
            }
#pragma unroll
            for (int fm = 0; fm < 2; fm++)
#pragma unroll
                for (int fn = 0; fn < 4; fn++)
                    MMA16816(acc[fm][fn], af[fm], bf[fn]);
        }
    }
#undef ISSUE_S

#pragma unroll
    for (int fm = 0; fm < 2; fm++) {
        int row0 = m0 + wm * 32 + fm * 16 + (lane >> 2);
#pragma unroll
        for (int fn = 0; fn < 4; fn++) {
            int col = n0 + wn * 32 + fn * 8 + (lane & 3) * 2;
            if (MODE == 1) {
                if (col < Nvalid) {
                    float2 b2 = *reinterpret_cast<const float2*>(bias + col);
                    float v0x = acc[fm][fn][0] + b2.x, v0y = acc[fm][fn][1] + b2.y;
                    float v1x = acc[fm][fn][2] + b2.x, v1y = acc[fm][fn][3] + b2.y;
                    *reinterpret_cast<float2*>(C + (size_t)row0 * ldC + col) = make_float2(v0x, v0y);
                    *reinterpret_cast<float2*>(C + (size_t)(row0 + 8) * ldC + col) = make_float2(v1x, v1y);
                    __nv_bfloat16 h0, l0, h1, l1;
                    split_bf16(v0x, h0, l0); split_bf16(v0y, h1, l1);
                    *reinterpret_cast<__nv_bfloat162*>(Ohi + (size_t)row0 * ldO + col) = __nv_bfloat162(h0, h1);
                    *reinterpret_cast<__nv_bfloat162*>(Olo + (size_t)row0 * ldO + col) = __nv_bfloat162(l0, l1);
                    split_bf16(v1x, h0, l0); split_bf16(v1y, h1, l1);
                    *reinterpret_cast<__nv_bfloat162*>(Ohi + (size_t)(row0 + 8) * ldO + col) = __nv_bfloat162(h0, h1);
                    *reinterpret_cast<__nv_bfloat162*>(Olo + (size_t)(row0 + 8) * ldO + col) = __nv_bfloat162(l0, l1);
                } else if (col < ldO) {
                    __nv_bfloat162 z(__float2bfloat16(0.f), __float2bfloat16(0.f));
                    *reinterpret_cast<__nv_bfloat162*>(Ohi + (size_t)row0 * ldO + col) = z;
                    *reinterpret_cast<__nv_bfloat162*>(Olo + (size_t)row0 * ldO + col) = z;
                    *reinterpret_cast<__nv_bfloat162*>(Ohi + (size_t)(row0 + 8) * ldO + col) = z;
                    *reinterpret_cast<__nv_bfloat162*>(Olo + (size_t)(row0 + 8) * ldO + col) = z;
                }
            } else {
                float2 b2 = *reinterpret_cast<const float2*>(bias + col);
                float v0x = acc[fm][fn][0] + b2.x, v0y = acc[fm][fn][1] + b2.y;
                float v1x = acc[fm][fn][2] + b2.x, v1y = acc[fm][fn][3] + b2.y;
                *reinterpret_cast<float2*>(C + (size_t)row0 * ldC + col) = make_float2(v0x, v0y);
                *reinterpret_cast<float2*>(C + (size_t)(row0 + 8) * ldC + col) = make_float2(v1x, v1y);
                if (MODE == 2) {
                    __nv_bfloat16 h0, l0, h1, l1;
                    split_bf16(v0x, h0, l0); split_bf16(v0y, h1, l1);
                    *reinterpret_cast<__nv_bfloat162*>(Ohi + (size_t)row0 * ldO + col) = __nv_bfloat162(h0, h1);
                    *reinterpret_cast<__nv_bfloat162*>(Olo + (size_t)row0 * ldO + col) = __nv_bfloat162(l0, l1);
                    split_bf16(v1x, h0, l0); split_bf16(v1y, h1, l1);
                    *reinterpret_cast<__nv_bfloat162*>(Ohi + (size_t)(row0 + 8) * ldO + col) = __nv_bfloat162(h0, h1);
                    *reinterpret_cast<__nv_bfloat162*>(Olo + (size_t)(row0 + 8) * ldO + col) = __nv_bfloat162(l0, l1);
                }
            }
        }
    }
}

// ---------------- launch -----------------------------------------------------
extern "C" void kernel_launch(void* const* d_in, const int* in_sizes, int n_in,
                              void* d_out, int out_size)
{
    const int*   x_t   = (const int*)  d_in[0];
    const float* etab  = (const float*)d_in[1];
    const float* Wi    = (const float*)d_in[2];
    const float* bi    = (const float*)d_in[3];
    const float* Wg    = (const float*)d_in[4];
    const float* bg    = (const float*)d_in[5];
    const float* Wo    = (const float*)d_in[6];
    const float* bo    = (const float*)d_in[7];
    const float* gamma = (const float*)d_in[8];
    const float* beta  = (const float*)d_in[9];
    const float* Wc    = (const float*)d_in[10];
    const float* bc    = (const float*)d_in[11];
    const float* Wr    = (const float*)d_in[12];
    const float* br    = (const float*)d_in[13];
    float* out = (float*)d_out;

    float* out_logits = out;
    float* out_recon  = out + (size_t)MROWS * VOCAB_;
    float* out_states = out_recon + (size_t)MROWS * D_;

    float *p_comb, *p_h;
    __nv_bfloat16 *p_xhi, *p_xlo, *p_c2hi, *p_c2lo, *p_ahi, *p_alo;
    __nv_bfloat16 *p_w1hi, *p_w1lo, *p_w2hi, *p_w2lo, *p_wrhi, *p_wrlo, *p_bchi, *p_bclo;
    cudaGetSymbolAddress((void**)&p_comb, g_comb);
    cudaGetSymbolAddress((void**)&p_h,    g_h);
    cudaGetSymbolAddress((void**)&p_xhi,  g_xhi);
    cudaGetSymbolAddress((void**)&p_xlo,  g_xlo);
    cudaGetSymbolAddress((void**)&p_c2hi, g_c2hi);
    cudaGetSymbolAddress((void**)&p_c2lo, g_c2lo);
    cudaGetSymbolAddress((void**)&p_ahi,  g_ahi);
    cudaGetSymbolAddress((void**)&p_alo,  g_alo);
    cudaGetSymbolAddress((void**)&p_w1hi, g_w1hi);
    cudaGetSymbolAddress((void**)&p_w1lo, g_w1lo);
    cudaGetSymbolAddress((void**)&p_w2hi, g_w2hi);
    cudaGetSymbolAddress((void**)&p_w2lo, g_w2lo);
    cudaGetSymbolAddress((void**)&p_wrhi, g_wrhi);
    cudaGetSymbolAddress((void**)&p_wrlo, g_wrlo);
    cudaGetSymbolAddress((void**)&p_bchi, g_bhi);
    cudaGetSymbolAddress((void**)&p_bclo, g_blo);

    cudaFuncSetAttribute(tc_gemm<D_, 0>, cudaFuncAttributeMaxDynamicSharedMemorySize,
                         GSTAGES * STAGE_BYTES);

    // 1: all small-weight preps in one launch
    prep_all<<<dim3(80, 9), 256>>>(Wi, Wo, Wr);
    // 2: Wc split (single launch)
    split_wc<<<dim3(VOCAB_ / 32, D_ / 32), 256>>>(Wc);
    // 3: embed (+ fused split)
    embed_kernel<<<MROWS, 64>>>(x_t, etab);

    for (int i = 0; i < DEPTH_; i++) {
        const float* bi_i = bi + (size_t)i * DS_;
        const float* Wg_i = Wg + (size_t)i * DS_ * S_;
        const float* bg_i = bg + (size_t)i * S_;
        const float* bo_i = bo + (size_t)i * D_;

        // 4 (i=0, profiled): GEMM1  comb = x @ WiT + bi  (N=264 guarded)
        tc_sm<D_, 1><<<dim3(NP1 / 64, MROWS / 64), 128>>>(
            p_xhi, p_xlo,
            p_w1hi + (size_t)i * NP1 * D_, p_w1lo + (size_t)i * NP1 * D_,
            bi_i, p_comb, DS_, p_c2hi, p_c2lo, KP2, DS_);
        gate_kernel<<<MROWS / 8, 256>>>(Wg_i, bg_i);
        scan_kernel<<<1, 1024>>>(out_states + (size_t)i * B_ * S_);
        // GEMM2: h = c2 @ WoT + bo  (fused x split for next layer)
        tc_sm<KP2, 2><<<dim3(D_ / 64, MROWS / 64), 128>>>(
            p_c2hi, p_c2lo,
            p_w2hi + (size_t)i * D_ * KP2, p_w2lo + (size_t)i * D_ * KP2,
            bo_i, p_h, D_, p_xhi, p_xlo, D_, D_);
    }

    ln_kernel<<<MROWS / 8, 256>>>(gamma, beta);

    // logits (dominant; 4-stage pipeline, streaming stores)
    tc_gemm<D_, 0><<<dim3(VOCAB_ / 128, MROWS / 128), 256, GSTAGES * STAGE_BYTES>>>(
        p_ahi, p_alo, p_bchi, p_bclo, bc, out_logits, VOCAB_);
    // recon
    tc_sm<D_, 0><<<dim3(D_ / 64, MROWS / 64), 128>>>(
        p_ahi, p_alo, p_wrhi, p_wrlo, br, out_recon, D_,
        (__nv_bfloat16*)nullptr, (__nv_bfloat16*)nullptr, 0, D_);
}

// round 17
// speedup vs baseline: 1.0878x; 1.0878x over previous
#include <cuda_runtime.h>
#include <cuda_bf16.h>
#include <cstdint>

#define D_     256
#define S_     8
#define DS_    264
#define DEPTH_ 4
#define VOCAB_ 32000
#define MROWS  4096
#define L_     2048
#define B_     2
#define KP2    288   // padded K for GEMM2
#define NP1    320   // padded N for GEMM1 B panel (5 x 64)

// ---------------- scratch (device globals) ----------------------------------
__device__ float g_h[MROWS * D_];             // h fp32 (ln input)
__device__ float g_comb[MROWS * DS_];         // combined fp32 (gate input)
__device__ float g_ga[S_ * MROWS];            // gates col-major [s][row]
__device__ float g_gb[S_ * MROWS];            // (1-g)*state_in col-major
__device__ __nv_bfloat16 g_xhi[MROWS * D_];   // h split hi (GEMM1 A)
__device__ __nv_bfloat16 g_xlo[MROWS * D_];
__device__ __nv_bfloat16 g_c2hi[MROWS * KP2]; // comb split (GEMM2 A), K padded
__device__ __nv_bfloat16 g_c2lo[MROWS * KP2];
__device__ __nv_bfloat16 g_ahi[MROWS * D_];   // ln output split (logits/recon A)
__device__ __nv_bfloat16 g_alo[MROWS * D_];
// weight splits, B layout [Npad][KPAD]
__device__ __nv_bfloat16 g_w1hi[DEPTH_ * NP1 * D_];   // WiT (264->320 rows)
__device__ __nv_bfloat16 g_w1lo[DEPTH_ * NP1 * D_];
__device__ __nv_bfloat16 g_w2hi[DEPTH_ * D_ * KP2];   // WoT (K 264->288)
__device__ __nv_bfloat16 g_w2lo[DEPTH_ * D_ * KP2];
__device__ __nv_bfloat16 g_wrhi[D_ * D_];             // WrT
__device__ __nv_bfloat16 g_wrlo[D_ * D_];
__device__ __nv_bfloat16 g_bhi[VOCAB_ * D_];          // WcT
__device__ __nv_bfloat16 g_blo[VOCAB_ * D_];

// ---------------- PTX helpers (baseline sm_80-era only) ----------------------
__device__ __forceinline__ uint32_t smem_u32(const void* p) {
    uint32_t a;
    asm("{ .reg .u64 t; cvta.to.shared.u64 t, %1; cvt.u32.u64 %0, t; }" : "=r"(a) : "l"(p));
    return a;
}
#define CP_ASYNC16(dst, src) \
    asm volatile("cp.async.cg.shared.global [%0], [%1], 16;" :: "r"(dst), "l"(src))
#define CP_COMMIT() asm volatile("cp.async.commit_group;" ::: "memory")
__device__ __forceinline__ void cp_wait_n(int n) {
    if (n <= 0)      asm volatile("cp.async.wait_group 0;" ::: "memory");
    else if (n == 1) asm volatile("cp.async.wait_group 1;" ::: "memory");
    else             asm volatile("cp.async.wait_group 2;" ::: "memory");
}
#define LDSM4(r0, r1, r2, r3, addr) \
    asm volatile("ldmatrix.sync.aligned.m8n8.x4.shared.b16 {%0,%1,%2,%3}, [%4];" \
                 : "=r"(r0), "=r"(r1), "=r"(r2), "=r"(r3) : "r"(addr))
#define MMA16816(d, a, b) \
    asm volatile("mma.sync.aligned.m16n8k16.row.col.f32.bf16.bf16.f32 " \
                 "{%0,%1,%2,%3}, {%4,%5,%6,%7}, {%8,%9}, {%0,%1,%2,%3};" \
                 : "+f"((d)[0]), "+f"((d)[1]), "+f"((d)[2]), "+f"((d)[3]) \
                 : "r"((a)[0]), "r"((a)[1]), "r"((a)[2]), "r"((a)[3]), \
                   "r"((b)[0]), "r"((b)[1]))
#define STG2CS(ptr, vx, vy) \
    asm volatile("st.global.cs.v2.f32 [%0], {%1,%2};" :: "l"(ptr), "f"(vx), "f"(vy) : "memory")

__device__ __forceinline__ void split_bf16(float v, __nv_bfloat16& hi, __nv_bfloat16& lo) {
    hi = __float2bfloat16(v);
    lo = __float2bfloat16(v - __bfloat162float(hi));
}

// ---------------- prep_all: all 9 weight transpose+splits in ONE launch ------
__global__ void __launch_bounds__(256)
prep_all(const float* __restrict__ Wi, const float* __restrict__ Wo,
         const float* __restrict__ Wr)
{
    int id = blockIdx.y;
    const float* src;
    __nv_bfloat16 *dhi, *dlo;
    int Ksrc, Nsrc, srcld, Npad, KP;
    if (id < 4) {
        src = Wi + (size_t)id * D_ * DS_;
        dhi = g_w1hi + (size_t)id * NP1 * D_; dlo = g_w1lo + (size_t)id * NP1 * D_;
        Ksrc = D_; Nsrc = DS_; srcld = DS_; Npad = NP1; KP = D_;
    } else if (id < 8) {
        int i = id - 4;
        src = Wo + (size_t)i * DS_ * D_;
        dhi = g_w2hi + (size_t)i * D_ * KP2; dlo = g_w2lo + (size_t)i * D_ * KP2;
        Ksrc = DS_; Nsrc = D_; srcld = D_; Npad = D_; KP = KP2;
    } else {
        src = Wr;
        dhi = g_wrhi; dlo = g_wrlo;
        Ksrc = D_; Nsrc = D_; srcld = D_; Npad = D_; KP = D_;
    }
    int nx = Npad / 32, ny = KP / 32;
    if ((int)blockIdx.x >= nx * ny) return;
    int n0 = ((int)blockIdx.x % nx) * 32;
    int k0 = ((int)blockIdx.x / nx) * 32;

    __shared__ float tile[32][33];
    int tx = threadIdx.x & 31, ty = threadIdx.x >> 5;
#pragma unroll
    for (int i = 0; i < 4; i++) {
        int k = k0 + ty + i * 8, n = n0 + tx;
        tile[ty + i * 8][tx] = (k < Ksrc && n < Nsrc) ? src[(size_t)k * srcld + n] : 0.f;
    }
    __syncthreads();
#pragma unroll
    for (int i = 0; i < 4; i++) {
        int n = n0 + ty + i * 8, k = k0 + tx;
        float x = tile[tx][ty + i * 8];
        __nv_bfloat16 hi, lo;
        split_bf16(x, hi, lo);
        dhi[(size_t)n * KP + k] = hi;
        dlo[(size_t)n * KP + k] = lo;
    }
}

// ---------------- Wc transpose + split (single launch) -----------------------
__global__ void __launch_bounds__(256)
split_wc(const float* __restrict__ Wc)
{
    __shared__ float tile[32][33];
    int tx = threadIdx.x & 31, ty = threadIdx.x >> 5;
    int v0 = blockIdx.x * 32, d0 = blockIdx.y * 32;
#pragma unroll
    for (int i = 0; i < 4; i++) {
        int d = d0 + ty + i * 8;
        tile[ty + i * 8][tx] = Wc[(size_t)d * VOCAB_ + v0 + tx];
    }
    __syncthreads();
#pragma unroll
    for (int i = 0; i < 4; i++) {
        int v = v0 + ty + i * 8;
        float x = tile[tx][ty + i * 8];
        __nv_bfloat16 hi, lo;
        split_bf16(x, hi, lo);
        g_bhi[(size_t)v * D_ + d0 + tx] = hi;
        g_blo[(size_t)v * D_ + d0 + tx] = lo;
    }
}

// ---------------- embed: gather + fused hi/lo split --------------------------
__global__ void embed_kernel(const int* __restrict__ x, const float* __restrict__ tab)
{
    int row = blockIdx.x;
    int t   = threadIdx.x;  // 64 threads x float4
    int tok = x[row];
    float4 v = reinterpret_cast<const float4*>(tab + (size_t)tok * D_)[t];
    reinterpret_cast<float4*>(g_h + (size_t)row * D_)[t] = v;
    __nv_bfloat16 h0, l0, h1, l1, h2, l2, h3, l3;
    split_bf16(v.x, h0, l0); split_bf16(v.y, h1, l1);
    split_bf16(v.z, h2, l2); split_bf16(v.w, h3, l3);
    __nv_bfloat162* hp = reinterpret_cast<__nv_bfloat162*>(g_xhi + (size_t)row * D_ + t * 4);
    __nv_bfloat162* lp = reinterpret_cast<__nv_bfloat162*>(g_xlo + (size_t)row * D_ + t * 4);
    hp[0] = __nv_bfloat162(h0, h1); hp[1] = __nv_bfloat162(h2, h3);
    lp[0] = __nv_bfloat162(l0, l1); lp[1] = __nv_bfloat162(l2, l3);
}

// ---------------- gate: sigmoid + compact scan inputs ------------------------
__global__ void gate_kernel(const float* __restrict__ Wg, const float* __restrict__ bg)
{
    int warp = (blockIdx.x * blockDim.x + threadIdx.x) >> 5;
    int lane = threadIdx.x & 31;
    if (warp >= MROWS) return;
    const float* row = g_comb + (size_t)warp * DS_;
    float acc[S_];
#pragma unroll
    for (int s = 0; s < S_; s++) acc[s] = 0.f;
    for (int k = lane; k < DS_; k += 32) {
        float c = row[k];
        const float* w = Wg + (size_t)k * S_;
#pragma unroll
        for (int s = 0; s < S_; s++) acc[s] += c * w[s];
    }
#pragma unroll
    for (int s = 0; s < S_; s++)
#pragma unroll
        for (int o = 16; o > 0; o >>= 1)
            acc[s] += __shfl_down_sync(0xffffffffu, acc[s], o);
    if (lane == 0) {
#pragma unroll
        for (int s = 0; s < S_; s++) {
            float g = 1.f / (1.f + __expf(-(acc[s] + bg[s])));
            float sin_v = row[D_ + s];
            g_ga[(size_t)s * MROWS + warp] = g;
            g_gb[(size_t)s * MROWS + warp] = (1.f - g) * sin_v;
        }
    }
}

// ---------------- scan: states -> c2 hi/lo (GEMM2 A) + final states ----------
__global__ void __launch_bounds__(1024)
scan_kernel(float* __restrict__ out_states)
{
    __shared__ float warp_tot[16];
    int w = threadIdx.x >> 5;
    int lane = threadIdx.x & 31;
    int pair = w >> 1;
    int half = w & 1;
    int b = pair >> 3, s = pair & 7;
    const float* ga = g_ga + (size_t)s * MROWS + (size_t)b * L_ + half * 1024;
    const float* gb = g_gb + (size_t)s * MROWS + (size_t)b * L_ + half * 1024;
    int l0 = lane * 32;

    float A = 1.f, Bv = 0.f;
#pragma unroll
    for (int i4 = 0; i4 < 8; i4++) {
        float4 gv = *reinterpret_cast<const float4*>(ga + l0 + i4 * 4);
        float4 bv = *reinterpret_cast<const float4*>(gb + l0 + i4 * 4);
        Bv = gv.x * Bv + bv.x; A *= gv.x;
        Bv = gv.y * Bv + bv.y; A *= gv.y;
        Bv = gv.z * Bv + bv.z; A *= gv.z;
        Bv = gv.w * Bv + bv.w; A *= gv.w;
    }
#pragma unroll
    for (int o = 1; o < 32; o <<= 1) {
        float Ap = __shfl_up_sync(0xffffffffu, A, o);
        float Bp = __shfl_up_sync(0xffffffffu, Bv, o);
        if (lane >= o) { Bv = A * Bp + Bv; A = A * Ap; }
    }
    if (half == 0 && lane == 31) warp_tot[pair] = Bv;
    __syncthreads();
    float y_w = (half == 0) ? 0.f : warp_tot[pair];
    float Aex = __shfl_up_sync(0xffffffffu, A, 1);
    float Bex = __shfl_up_sync(0xffffffffu, Bv, 1);
    if (lane == 0) { Aex = 1.f; Bex = 0.f; }
    float y = Aex * y_w + Bex;

    size_t rbase = (size_t)b * L_ + half * 1024 + l0;
#pragma unroll
    for (int i4 = 0; i4 < 8; i4++) {
        float4 gv = *reinterpret_cast<const float4*>(ga + l0 + i4 * 4);
        float4 bv = *reinterpret_cast<const float4*>(gb + l0 + i4 * 4);
        float ys[4];
        y = gv.x * y + bv.x; ys[0] = y;
        y = gv.y * y + bv.y; ys[1] = y;
        y = gv.z * y + bv.z; ys[2] = y;
        y = gv.w * y + bv.w; ys[3] = y;
#pragma unroll
        for (int j = 0; j < 4; j++) {
            __nv_bfloat16 hi, lo;
            split_bf16(ys[j], hi, lo);
            size_t idx = (rbase + i4 * 4 + j) * KP2 + D_ + s;
            g_c2hi[idx] = hi;
            g_c2lo[idx] = lo;
        }
    }
    if (half == 1 && lane == 31) out_states[b * S_ + s] = y;
}

// ---------------- layernorm: h fp32 -> ahi/alo -------------------------------
__global__ void ln_kernel(const float* __restrict__ gamma, const float* __restrict__ beta)
{
    int warp = (blockIdx.x * blockDim.x + threadIdx.x) >> 5;
    int lane = threadIdx.x & 31;
    if (warp >= MROWS) return;
    const float* x = g_h + (size_t)warp * D_;
    float v[8];
    *reinterpret_cast<float4*>(v)     = *reinterpret_cast<const float4*>(x + lane * 8);
    *reinterpret_cast<float4*>(v + 4) = *reinterpret_cast<const float4*>(x + lane * 8 + 4);
    float sum = 0.f;
#pragma unroll
    for (int i = 0; i < 8; i++) sum += v[i];
#pragma unroll
    for (int o = 16; o > 0; o >>= 1) sum += __shfl_xor_sync(0xffffffffu, sum, o);
    float mu = sum * (1.f / 256.f);
    float sq = 0.f;
#pragma unroll
    for (int i = 0; i < 8; i++) { float d = v[i] - mu; sq += d * d; }
#pragma unroll
    for (int o = 16; o > 0; o >>= 1) sq += __shfl_xor_sync(0xffffffffu, sq, o);
    float rstd = rsqrtf(sq * (1.f / 256.f) + 1e-5f);
    __nv_bfloat16* hip = g_ahi + (size_t)warp * D_;
    __nv_bfloat16* lop = g_alo + (size_t)warp * D_;
#pragma unroll
    for (int i = 0; i < 8; i++) {
        int c = lane * 8 + i;
        float y = (v[i] - mu) * rstd * gamma[c] + beta[c];
        __nv_bfloat16 hi, lo;
        split_bf16(y, hi, lo);
        hip[c] = hi;
        lop[c] = lo;
    }
}

// ---------------- tc_gemm: 128x128 tile, FUSED 3-term per k-chunk ------------
// Per chunk: load Ahi/Alo/Bhi/Blo tiles (32KB), compute AhiBhi+AhiBlo+AloBhi.
// 8 iterations instead of 24; A-fragment registers reused for Alo.
#define GSTAGE_BYTES 32768
#define GSTAGES 3
template<int KPAD, int MODE>
__global__ void __launch_bounds__(256)
tc_gemm(const __nv_bfloat16* __restrict__ Ahi, const __nv_bfloat16* __restrict__ Alo,
        const __nv_bfloat16* __restrict__ Bhi, const __nv_bfloat16* __restrict__ Blo,
        const float* __restrict__ bias,
        float* __restrict__ C, int ldC)
{
    constexpr int NCH = KPAD / 32;
    extern __shared__ char smem[];
    uint32_t sb = smem_u32(smem);
    int tid = threadIdx.x;
    int lane = tid & 31;
    int warp = tid >> 5;
    int wm = warp >> 2;
    int wn = warp & 3;
    int m0 = blockIdx.y * 128;
    int n0 = blockIdx.x * 128;

    int st_r0 = tid >> 2;
    int st_r1 = st_r0 + 64;
    int st_c  = tid & 3;
    uint32_t st_off0 = (uint32_t)(st_r0 * 64 + ((st_c ^ ((st_r0 >> 1) & 3)) << 4));
    uint32_t st_off1 = (uint32_t)(st_r1 * 64 + ((st_c ^ ((st_r1 >> 1) & 3)) << 4));

    int arow[4], brow[2];
    uint32_t aswz[4], bswz[2];
#pragma unroll
    for (int fm = 0; fm < 4; fm++) {
        int r = wm * 64 + fm * 16 + (lane & 15);
        arow[fm] = r * 64;
        aswz[fm] = (r >> 1) & 3;
    }
#pragma unroll
    for (int g = 0; g < 2; g++) {
        int r = wn * 32 + g * 16 + (lane & 15);
        brow[g] = r * 64;
        bswz[g] = (r >> 1) & 3;
    }
    uint32_t chi = (uint32_t)(lane >> 4);

    float acc[4][4][4];
#pragma unroll
    for (int i = 0; i < 4; i++)
#pragma unroll
        for (int j = 0; j < 4; j++)
#pragma unroll
            for (int r = 0; r < 4; r++) acc[i][j][r] = 0.f;

    // stage layout: Ahi@0, Alo@8192, Bhi@16384, Blo@24576
#define ISSUE(ci, stg)                                                                   \
    do {                                                                                 \
        int _kc = (ci) * 32;                                                             \
        uint32_t _s = sb + (stg) * GSTAGE_BYTES;                                         \
        const __nv_bfloat16* _a0 = Ahi + (size_t)(m0 + st_r0) * KPAD + _kc + st_c * 8;   \
        const __nv_bfloat16* _a1 = Ahi + (size_t)(m0 + st_r1) * KPAD + _kc + st_c * 8;   \
        const __nv_bfloat16* _b0 = Bhi + (size_t)(n0 + st_r0) * KPAD + _kc + st_c * 8;   \
        const __nv_bfloat16* _b1 = Bhi + (size_t)(n0 + st_r1) * KPAD + _kc + st_c * 8;   \
        CP_ASYNC16(_s + st_off0, _a0);                                                   \
        CP_ASYNC16(_s + st_off1, _a1);                                                   \
        CP_ASYNC16(_s + 8192 + st_off0, _a0 + (Alo - Ahi));                              \
        CP_ASYNC16(_s + 8192 + st_off1, _a1 + (Alo - Ahi));                              \
        CP_ASYNC16(_s + 16384 + st_off0, _b0);                                           \
        CP_ASYNC16(_s + 16384 + st_off1, _b1);                                           \
        CP_ASYNC16(_s + 24576 + st_off0, _b0 + (Blo - Bhi));                             \
        CP_ASYNC16(_s + 24576 + st_off1, _b1 + (Blo - Bhi));                             \
    } while (0)

#pragma unroll
    for (int p = 0; p < GSTAGES - 1; p++) { ISSUE(p, p); CP_COMMIT(); }

    for (int ci = 0; ci < NCH; ci++) {
        int rem = NCH - 1 - ci;
        cp_wait_n(rem < GSTAGES - 2 ? rem : GSTAGES - 2);
        __syncthreads();
        if (ci + GSTAGES - 1 < NCH) ISSUE(ci + GSTAGES - 1, (ci + GSTAGES - 1) % GSTAGES);
        CP_COMMIT();

        uint32_t s0 = sb + (ci % GSTAGES) * GSTAGE_BYTES;
#pragma unroll
        for (int ks = 0; ks < 2; ks++) {
            uint32_t c = 2 * ks + chi;
            uint32_t af[4][4], bfh[4][2], bfl[4][2];
#pragma unroll
            for (int fm = 0; fm < 4; fm++) {
                uint32_t addr = s0 + arow[fm] + ((c ^ aswz[fm]) << 4);
                LDSM4(af[fm][0], af[fm][1], af[fm][2], af[fm][3], addr);
            }
#pragma unroll
            for (int g = 0; g < 2; g++) {
                uint32_t addr = s0 + 16384 + brow[g] + ((c ^ bswz[g]) << 4);
                uint32_t t0, t1, t2, t3;
                LDSM4(t0, t1, t2, t3, addr);
                bfh[2 * g + 0][0] = t0; bfh[2 * g + 1][0] = t1;
                bfh[2 * g + 0][1] = t2; bfh[2 * g + 1][1] = t3;
            }
#pragma unroll
            for (int g = 0; g < 2; g++) {
                uint32_t addr = s0 + 24576 + brow[g] + ((c ^ bswz[g]) << 4);
                uint32_t t0, t1, t2, t3;
                LDSM4(t0, t1, t2, t3, addr);
                bfl[2 * g + 0][0] = t0; bfl[2 * g + 1][0] = t1;
                bfl[2 * g + 0][1] = t2; bfl[2 * g + 1][1] = t3;
            }
            // Ahi x Bhi, Ahi x Blo
#pragma unroll
            for (int fm = 0; fm < 4; fm++)
#pragma unroll
                for (int fn = 0; fn < 4; fn++) {
                    MMA16816(acc[fm][fn], af[fm], bfh[fn]);
                    MMA16816(acc[fm][fn], af[fm], bfl[fn]);
                }
            // reuse af for Alo
#pragma unroll
            for (int fm = 0; fm < 4; fm++) {
                uint32_t addr = s0 + 8192 + arow[fm] + ((c ^ aswz[fm]) << 4);
                LDSM4(af[fm][0], af[fm][1], af[fm][2], af[fm][3], addr);
            }
#pragma unroll
            for (int fm = 0; fm < 4; fm++)
#pragma unroll
                for (int fn = 0; fn < 4; fn++)
                    MMA16816(acc[fm][fn], af[fm], bfh[fn]);
        }
    }
#undef ISSUE

#pragma unroll
    for (int fm = 0; fm < 4; fm++) {
        int row0 = m0 + wm * 64 + fm * 16 + (lane >> 2);
#pragma unroll
        for (int fn = 0; fn < 4; fn++) {
            int col = n0 + wn * 32 + fn * 8 + (lane & 3) * 2;
            float2 b2 = *reinterpret_cast<const float2*>(bias + col);
            float v0x = acc[fm][fn][0] + b2.x, v0y = acc[fm][fn][1] + b2.y;
            float v1x = acc[fm][fn][2] + b2.x, v1y = acc[fm][fn][3] + b2.y;
            STG2CS(C + (size_t)row0 * ldC + col, v0x, v0y);
            STG2CS(C + (size_t)(row0 + 8) * ldC + col, v1x, v1y);
        }
    }
}

// ---------------- tc_sm: 64x64 tile, FUSED 3-term per k-chunk ----------------
#define SSTAGE_BYTES 16384
#define SSTAGES 3
template<int KPAD, int MODE>
__global__ void __launch_bounds__(128)
tc_sm(const __nv_bfloat16* __restrict__ Ahi, const __nv_bfloat16* __restrict__ Alo,
      const __nv_bfloat16* __restrict__ Bhi, const __nv_bfloat16* __restrict__ Blo,
      const float* __restrict__ bias,
      float* __restrict__ C, int ldC,
      __nv_bfloat16* __restrict__ Ohi, __nv_bfloat16* __restrict__ Olo,
      int ldO, int Nvalid)
{
    constexpr int NCH = KPAD / 32;
    __shared__ char smem[SSTAGES * SSTAGE_BYTES];
    uint32_t sb = smem_u32(smem);
    int tid = threadIdx.x;
    int lane = tid & 31;
    int warp = tid >> 5;
    int wm = warp >> 1;          // 0..1
    int wn = warp & 1;           // 0..1
    int m0 = blockIdx.y * 64;
    int n0 = blockIdx.x * 64;

    int st_r = tid >> 1;
    int st_c0 = (tid & 1) * 2;
    uint32_t st_off0 = (uint32_t)(st_r * 64 + ((st_c0 ^ ((st_r >> 1) & 3)) << 4));
    uint32_t st_off1 = (uint32_t)(st_r * 64 + (((st_c0 + 1) ^ ((st_r >> 1) & 3)) << 4));

    int arow[2], brow[2];
    uint32_t aswz[2], bswz[2];
#pragma unroll
    for (int fm = 0; fm < 2; fm++) {
        int r = wm * 32 + fm * 16 + (lane & 15);
        arow[fm] = r * 64;
        aswz[fm] = (r >> 1) & 3;
    }
#pragma unroll
    for (int g = 0; g < 2; g++) {
        int r = wn * 32 + g * 16 + (lane & 15);
        brow[g] = r * 64;
        bswz[g] = (r >> 1) & 3;
    }
    uint32_t chi = (uint32_t)(lane >> 4);

    float acc[2][4][4];
#pragma unroll
    for (int i = 0; i < 2; i++)
#pragma unroll
        for (int j = 0; j < 4; j++)
#pragma unroll
            for (int r = 0; r < 4; r++) acc[i][j][r] = 0.f;

    // stage layout: Ahi@0, Alo@4096, Bhi@8192, Blo@12288
#define ISSUE_S(ci, stg)                                                                   \
    do {                                                                                   \
        int _kc = (ci) * 32;                                                               \
        uint32_t _s = sb + (stg) * SSTAGE_BYTES;                                           \
        const __nv_bfloat16* _a0 = Ahi + (size_t)(m0 + st_r) * KPAD + _kc + st_c0 * 8;     \
        const __nv_bfloat16* _b0 = Bhi + (size_t)(n0 + st_r) * KPAD + _kc + st_c0 * 8;     \
        CP_ASYNC16(_s + st_off0, _a0);                                                     \
        CP_ASYNC16(_s + st_off1, _a0 + 8);                                                 \
        CP_ASYNC16(_s + 4096 + st_off0, _a0 + (Alo - Ahi));                                \
        CP_ASYNC16(_s + 4096 + st_off1, _a0 + (Alo - Ahi) + 8);                            \
        CP_ASYNC16(_s + 8192 + st_off0, _b0);                                              \
        CP_ASYNC16(_s + 8192 + st_off1, _b0 + 8);                                          \
        CP_ASYNC16(_s + 12288 + st_off0, _b0 + (Blo - Bhi));                               \
        CP_ASYNC16(_s + 12288 + st_off1, _b0 + (Blo - Bhi) + 8);                           \
    } while (0)

#pragma unroll
    for (int p = 0; p < SSTAGES - 1; p++) { ISSUE_S(p, p); CP_COMMIT(); }

    for (int ci = 0; ci < NCH; ci++) {
        int rem = NCH - 1 - ci;
        cp_wait_n(rem < SSTAGES - 2 ? rem : SSTAGES - 2);
        __syncthreads();
        if (ci + SSTAGES - 1 < NCH) ISSUE_S(ci + SSTAGES - 1, (ci + SSTAGES - 1) % SSTAGES);
        CP_COMMIT();

        uint32_t s0 = sb + (ci % SSTAGES) * SSTAGE_BYTES;
#pragma unroll
        for (int ks = 0; ks < 2; ks++) {
            uint32_t c = 2 * ks + chi;
            uint32_t af[2][4], bfh[4][2], bfl[4][2];
#pragma unroll
            for (int fm = 0; fm < 2; fm++) {
                uint32_t addr = s0 + arow[fm] + ((c ^ aswz[fm]) << 4);
                LDSM4(af[fm][0], af[fm][1], af[fm][2], af[fm][3], addr);
            }
#pragma unroll
            for (int g = 0; g < 2; g++) {
                uint32_t addr = s0 + 8192 + brow[g] + ((c ^ bswz[g]) << 4);
                uint32_t t0, t1, t2, t3;
                LDSM4(t0, t1, t2, t3, addr);
                bfh[2 * g + 0][0] = t0; bfh[2 * g + 1][0] = t1;
                bfh[2 * g + 0][1] = t2; bfh[2 * g + 1][1] = t3;
            }
#pragma unroll
            for (int g = 0; g < 2; g++) {
                uint32_t addr = s0 + 12288 + brow[g] + ((c ^ bswz[g]) << 4);
                uint32_t t0, t1, t2, t3;
                LDSM4(t0, t1, t2, t3, addr);
                bfl[2 * g + 0][0] = t0; bfl[2 * g + 1][0] = t1;
                bfl[2 * g + 0][1] = t2; bfl[2 * g + 1][1] = t3;
            }
#pragma unroll
            for (int fm = 0; fm < 2; fm++)
#pragma unroll
                for (int fn = 0; fn < 4; fn++) {
                    MMA16816(acc[fm][fn], af[fm], bfh[fn]);
                    MMA16816(acc[fm][fn], af[fm], bfl[fn]);
                }
#pragma unroll
            for (int fm = 0; fm < 2; fm++) {
                uint32_t addr = s0 + 4096 + arow[fm] + ((c ^ aswz[fm]) << 4);
                LDSM4(af[fm][0], af[fm][1], af[fm][2], af[fm][3], addr);
            }
#pragma unroll
            for (int fm = 0; fm < 2; fm++)
#pragma unroll
                for (int fn = 0; fn < 4; fn++)
                    MMA16816(acc[fm][fn], af[fm], bfh[fn]);
        }
    }
#undef ISSUE_S

#pragma unroll
    for (int fm = 0; fm < 2; fm++) {
        int row0 = m0 + wm * 32 + fm * 16 + (lane >> 2);
#pragma unroll
        for (int fn = 0; fn < 4; fn++) {
            int col = n0 + wn * 32 + fn * 8 + (lane & 3) * 2;
            if (MODE == 1) {
                if (col < Nvalid) {
                    float2 b2 = *reinterpret_cast<const float2*>(bias + col);
                    float v0x = acc[fm][fn][0] + b2.x, v0y = acc[fm][fn][1] + b2.y;
                    float v1x = acc[fm][fn][2] + b2.x, v1y = acc[fm][fn][3] + b2.y;
                    *reinterpret_cast<float2*>(C + (size_t)row0 * ldC + col) = make_float2(v0x, v0y);
                    *reinterpret_cast<float2*>(C + (size_t)(row0 + 8) * ldC + col) = make_float2(v1x, v1y);
                    __nv_bfloat16 h0, l0, h1, l1;
                    split_bf16(v0x, h0, l0); split_bf16(v0y, h1, l1);
                    *reinterpret_cast<__nv_bfloat162*>(Ohi + (size_t)row0 * ldO + col) = __nv_bfloat162(h0, h1);
                    *reinterpret_cast<__nv_bfloat162*>(Olo + (size_t)row0 * ldO + col) = __nv_bfloat162(l0, l1);
                    split_bf16(v1x, h0, l0); split_bf16(v1y, h1, l1);
                    *reinterpret_cast<__nv_bfloat162*>(Ohi + (size_t)(row0 + 8) * ldO + col) = __nv_bfloat162(h0, h1);
                    *reinterpret_cast<__nv_bfloat162*>(Olo + (size_t)(row0 + 8) * ldO + col) = __nv_bfloat162(l0, l1);
                } else if (col < ldO) {
                    __nv_bfloat162 z(__float2bfloat16(0.f), __float2bfloat16(0.f));
                    *reinterpret_cast<__nv_bfloat162*>(Ohi + (size_t)row0 * ldO + col) = z;
                    *reinterpret_cast<__nv_bfloat162*>(Olo + (size_t)row0 * ldO + col) = z;
                    *reinterpret_cast<__nv_bfloat162*>(Ohi + (size_t)(row0 + 8) * ldO + col) = z;
                    *reinterpret_cast<__nv_bfloat162*>(Olo + (size_t)(row0 + 8) * ldO + col) = z;
                }
            } else {
                float2 b2 = *reinterpret_cast<const float2*>(bias + col);
                float v0x = acc[fm][fn][0] + b2.x, v0y = acc[fm][fn][1] + b2.y;
                float v1x = acc[fm][fn][2] + b2.x, v1y = acc[fm][fn][3] + b2.y;
                *reinterpret_cast<float2*>(C + (size_t)row0 * ldC + col) = make_float2(v0x, v0y);
                *reinterpret_cast<float2*>(C + (size_t)(row0 + 8) * ldC + col) = make_float2(v1x, v1y);
                if (MODE == 2) {
                    __nv_bfloat16 h0, l0, h1, l1;
                    split_bf16(v0x, h0, l0); split_bf16(v0y, h1, l1);
                    *reinterpret_cast<__nv_bfloat162*>(Ohi + (size_t)row0 * ldO + col) = __nv_bfloat162(h0, h1);
                    *reinterpret_cast<__nv_bfloat162*>(Olo + (size_t)row0 * ldO + col) = __nv_bfloat162(l0, l1);
                    split_bf16(v1x, h0, l0); split_bf16(v1y, h1, l1);
                    *reinterpret_cast<__nv_bfloat162*>(Ohi + (size_t)(row0 + 8) * ldO + col) = __nv_bfloat162(h0, h1);
                    *reinterpret_cast<__nv_bfloat162*>(Olo + (size_t)(row0 + 8) * ldO + col) = __nv_bfloat162(l0, l1);
                }
            }
        }
    }
}

// ---------------- launch -----------------------------------------------------
extern "C" void kernel_launch(void* const* d_in, const int* in_sizes, int n_in,
                              void* d_out, int out_size)
{
    const int*   x_t   = (const int*)  d_in[0];
    const float* etab  = (const float*)d_in[1];
    const float* Wi    = (const float*)d_in[2];
    const float* bi    = (const float*)d_in[3];
    const float* Wg    = (const float*)d_in[4];
    const float* bg    = (const float*)d_in[5];
    const float* Wo    = (const float*)d_in[6];
    const float* bo    = (const float*)d_in[7];
    const float* gamma = (const float*)d_in[8];
    const float* beta  = (const float*)d_in[9];
    const float* Wc    = (const float*)d_in[10];
    const float* bc    = (const float*)d_in[11];
    const float* Wr    = (const float*)d_in[12];
    const float* br    = (const float*)d_in[13];
    float* out = (float*)d_out;

    float* out_logits = out;
    float* out_recon  = out + (size_t)MROWS * VOCAB_;
    float* out_states = out_recon + (size_t)MROWS * D_;

    float *p_comb, *p_h;
    __nv_bfloat16 *p_xhi, *p_xlo, *p_c2hi, *p_c2lo, *p_ahi, *p_alo;
    __nv_bfloat16 *p_w1hi, *p_w1lo, *p_w2hi, *p_w2lo, *p_wrhi, *p_wrlo, *p_bchi, *p_bclo;
    cudaGetSymbolAddress((void**)&p_comb, g_comb);
    cudaGetSymbolAddress((void**)&p_h,    g_h);
    cudaGetSymbolAddress((void**)&p_xhi,  g_xhi);
    cudaGetSymbolAddress((void**)&p_xlo,  g_xlo);
    cudaGetSymbolAddress((void**)&p_c2hi, g_c2hi);
    cudaGetSymbolAddress((void**)&p_c2lo, g_c2lo);
    cudaGetSymbolAddress((void**)&p_ahi,  g_ahi);
    cudaGetSymbolAddress((void**)&p_alo,  g_alo);
    cudaGetSymbolAddress((void**)&p_w1hi, g_w1hi);
    cudaGetSymbolAddress((void**)&p_w1lo, g_w1lo);
    cudaGetSymbolAddress((void**)&p_w2hi, g_w2hi);
    cudaGetSymbolAddress((void**)&p_w2lo, g_w2lo);
    cudaGetSymbolAddress((void**)&p_wrhi, g_wrhi);
    cudaGetSymbolAddress((void**)&p_wrlo, g_wrlo);
    cudaGetSymbolAddress((void**)&p_bchi, g_bhi);
    cudaGetSymbolAddress((void**)&p_bclo, g_blo);

    cudaFuncSetAttribute(tc_gemm<D_, 0>, cudaFuncAttributeMaxDynamicSharedMemorySize,
                         GSTAGES * GSTAGE_BYTES);

    // 1: all small-weight preps in one launch
    prep_all<<<dim3(80, 9), 256>>>(Wi, Wo, Wr);
    // 2: Wc split (single launch)
    split_wc<<<dim3(VOCAB_ / 32, D_ / 32), 256>>>(Wc);
    // 3: embed (+ fused split)
    embed_kernel<<<MROWS, 64>>>(x_t, etab);

    for (int i = 0; i < DEPTH_; i++) {
        const float* bi_i = bi + (size_t)i * DS_;
        const float* Wg_i = Wg + (size_t)i * DS_ * S_;
        const float* bg_i = bg + (size_t)i * S_;
        const float* bo_i = bo + (size_t)i * D_;

        // 4 (i=0, profiled): GEMM1  comb = x @ WiT + bi  (N=264 guarded)
        tc_sm<D_, 1><<<dim3(NP1 / 64, MROWS / 64), 128>>>(
            p_xhi, p_xlo,
            p_w1hi + (size_t)i * NP1 * D_, p_w1lo + (size_t)i * NP1 * D_,
            bi_i, p_comb, DS_, p_c2hi, p_c2lo, KP2, DS_);
        gate_kernel<<<MROWS / 8, 256>>>(Wg_i, bg_i);
        scan_kernel<<<1, 1024>>>(out_states + (size_t)i * B_ * S_);
        // GEMM2: h = c2 @ WoT + bo  (fused x split for next layer)
        tc_sm<KP2, 2><<<dim3(D_ / 64, MROWS / 64), 128>>>(
            p_c2hi, p_c2lo,
            p_w2hi + (size_t)i * D_ * KP2, p_w2lo + (size_t)i * D_ * KP2,
            bo_i, p_h, D_, p_xhi, p_xlo, D_, D_);
    }

    ln_kernel<<<MROWS / 8, 256>>>(gamma, beta);

    // logits (dominant; fused 3-term, streaming stores)
    tc_gemm<D_, 0><<<dim3(VOCAB_ / 128, MROWS / 128), 256, GSTAGES * GSTAGE_BYTES>>>(
        p_ahi, p_alo, p_bchi, p_bclo, bc, out_logits, VOCAB_);
    // recon
    tc_sm<D_, 0><<<dim3(D_ / 64, MROWS / 64), 128>>>(
        p_ahi, p_alo, p_wrhi, p_wrlo, br, out_recon, D_,
        (__nv_bfloat16*)nullptr, (__nv_bfloat16*)nullptr, 0, D_);
}